// round 15
// baseline (speedup 1.0000x reference)
#include <cuda_runtime.h>
#include <cuda_bf16.h>
#include <math.h>
#include <stdint.h>

// Problem dims (fixed)
#define Vv 32000
#define Dd 1024
#define Bb 8
#define Tt 256
#define Mrows (Bb * Tt)   // 2048

// ---------------- scratch (static device globals; allocation-free) ----------
__device__ __nv_bfloat16 g_Xb[Mrows * Dd];
__device__ __nv_bfloat16 g_Wb[Dd * Dd];
__device__ __nv_bfloat16 g_Woutb[(size_t)Vv * Dd];
__device__ float g_Wx[Mrows * Dd];
__device__ __nv_bfloat16 g_hsb[Mrows * Dd];

#define RNN_CTAS 128
__device__ float g_h2[2][RNN_CTAS][64];      // producer-major h state
__device__ unsigned g_flags[RNN_CTAS * 8];   // 32B stride per flag

// ---------------- PTX helpers ----------------------------------------------
__device__ __forceinline__ uint32_t smem_u32(const void* p) {
    uint32_t a;
    asm("{ .reg .u64 t; cvta.to.shared.u64 t, %1; cvt.u32.u64 %0, t; }"
        : "=r"(a) : "l"(p));
    return a;
}

__device__ __forceinline__ void cp_async16(uint32_t dst, const void* src) {
    asm volatile("cp.async.cg.shared.global [%0], [%1], 16;" :: "r"(dst), "l"(src));
}
#define CP_COMMIT() asm volatile("cp.async.commit_group;" ::: "memory")
#define CP_WAIT(n)  asm volatile("cp.async.wait_group %0;" :: "n"(n) : "memory")

__device__ __forceinline__ void ldsm_x4(uint32_t& r0, uint32_t& r1,
                                        uint32_t& r2, uint32_t& r3, uint32_t addr) {
    asm volatile("ldmatrix.sync.aligned.m8n8.x4.shared.b16 {%0,%1,%2,%3}, [%4];"
                 : "=r"(r0), "=r"(r1), "=r"(r2), "=r"(r3) : "r"(addr));
}

__device__ __forceinline__ void mma16816(float& c0, float& c1, float& c2, float& c3,
                                         uint32_t a0, uint32_t a1, uint32_t a2, uint32_t a3,
                                         uint32_t b0, uint32_t b1) {
    asm volatile(
        "mma.sync.aligned.m16n8k16.row.col.f32.bf16.bf16.f32 "
        "{%0,%1,%2,%3}, {%4,%5,%6,%7}, {%8,%9}, {%0,%1,%2,%3};\n"
        : "+f"(c0), "+f"(c1), "+f"(c2), "+f"(c3)
        : "r"(a0), "r"(a1), "r"(a2), "r"(a3), "r"(b0), "r"(b1));
}

__device__ __forceinline__ unsigned ld_acquire(const unsigned* p) {
    unsigned v;
    asm volatile("ld.global.acquire.gpu.b32 %0, [%1];" : "=r"(v) : "l"(p) : "memory");
    return v;
}
__device__ __forceinline__ void st_release(unsigned* p, unsigned v) {
    asm volatile("st.global.release.gpu.b32 [%0], %1;" :: "l"(p), "r"(v) : "memory");
}

// ---------------- small helpers --------------------------------------------
__global__ void f32_to_bf16_kernel(const float4* __restrict__ src,
                                   __nv_bfloat162* __restrict__ dst, int n4) {
    for (int i = blockIdx.x * blockDim.x + threadIdx.x; i < n4;
         i += gridDim.x * blockDim.x) {
        float4 v = src[i];
        dst[2 * i]     = __floats2bfloat162_rn(v.x, v.y);
        dst[2 * i + 1] = __floats2bfloat162_rn(v.z, v.w);
    }
}

__global__ void gather_embed_kernel(const int* __restrict__ idx,
                                    const float* __restrict__ E,
                                    __nv_bfloat16* __restrict__ Xb) {
    int row = blockIdx.x;
    int v = idx[row];
    const float4* src = (const float4*)(E + (size_t)v * Dd);
    __nv_bfloat162* dst = (__nv_bfloat162*)(Xb + (size_t)row * Dd);
    for (int i = threadIdx.x; i < Dd / 4; i += blockDim.x) {
        float4 a = src[i];
        dst[2 * i]     = __floats2bfloat162_rn(a.x, a.y);
        dst[2 * i + 1] = __floats2bfloat162_rn(a.z, a.w);
    }
}

__global__ void rnn_reset_kernel() {
    int i = blockIdx.x * blockDim.x + threadIdx.x;
    if (i < RNN_CTAS * 64) ((float*)g_h2)[i] = 0.f;   // zero buffer 0
    if (i < RNN_CTAS) g_flags[i * 8] = 0u;
}

// ---------------- pipelined HMMA GEMM:  C[M,N] = A[M,K]*B[N,K]^T + bias[N] --
#define ROWB 80
#define A_BYTES (128 * ROWB)
#define STG (2 * A_BYTES)
#define S_ST 3
#define GEMM_SMEM (S_ST * STG + 128)

__device__ __forceinline__ void load_stage(const __nv_bfloat16* Ag,
                                           const __nv_bfloat16* Bg, int K,
                                           int kt, uint32_t base, int tid) {
    const int kbase = kt * 32;
#pragma unroll
    for (int i = 0; i < 2; i++) {
        int id = tid + i * 256;
        int row = id >> 2, seg = id & 3;
        uint32_t soff = row * ROWB + seg * 16;
        cp_async16(base + soff, Ag + (size_t)row * K + kbase + seg * 8);
        cp_async16(base + A_BYTES + soff, Bg + (size_t)row * K + kbase + seg * 8);
    }
}

__global__ __launch_bounds__(256, 2)
void gemm_bf16_kernel(const __nv_bfloat16* __restrict__ A,
                      const __nv_bfloat16* __restrict__ Bm,
                      const float* __restrict__ bias,
                      float* __restrict__ C, int M, int N, int K) {
    extern __shared__ char dsm[];
    uint32_t sb = (smem_u32(dsm) + 127) & ~127u;

    const int tid = threadIdx.x;
    const int warp = tid >> 5, lane = tid & 31;
    const int wm = warp >> 2, wn = warp & 3;
    const int bm = blockIdx.x, bn = blockIdx.y;
    const int NT = K / 32;

    const uint32_t aLane = (uint32_t)((lane & 15) * ROWB + ((lane >> 4) << 4));
    const uint32_t bLane = (uint32_t)((((lane >> 4) << 3) + (lane & 7)) * ROWB +
                                      (((lane >> 3) & 1) << 4));

    float acc[4][4][4];
#pragma unroll
    for (int mi = 0; mi < 4; mi++)
#pragma unroll
        for (int ni = 0; ni < 4; ni++)
#pragma unroll
            for (int q = 0; q < 4; q++) acc[mi][ni][q] = 0.f;

    const __nv_bfloat16* Ag = A + (size_t)(bm * 128) * K;
    const __nv_bfloat16* Bg = Bm + (size_t)(bn * 128) * K;

    load_stage(Ag, Bg, K, 0, sb, tid);
    CP_COMMIT();
    load_stage(Ag, Bg, K, 1, sb + STG, tid);
    CP_COMMIT();

    for (int kt = 0; kt < NT; kt++) {
        CP_WAIT(1);
        __syncthreads();

        const int ktn = kt + 2;
        if (ktn < NT)
            load_stage(Ag, Bg, K, ktn, sb + (ktn % S_ST) * STG, tid);
        CP_COMMIT();

        const uint32_t stage = sb + (kt % S_ST) * STG;
        const uint32_t aBase = stage + (wm * 64) * ROWB + aLane;
        const uint32_t bBase = stage + A_BYTES + (wn * 32) * ROWB + bLane;

#pragma unroll
        for (int ks = 0; ks < 64; ks += 32) {
            uint32_t af[4][4], bf[2][4];
#pragma unroll
            for (int mi = 0; mi < 4; mi++)
                ldsm_x4(af[mi][0], af[mi][1], af[mi][2], af[mi][3],
                        aBase + mi * 16 * ROWB + ks);
#pragma unroll
            for (int nb = 0; nb < 2; nb++)
                ldsm_x4(bf[nb][0], bf[nb][1], bf[nb][2], bf[nb][3],
                        bBase + nb * 16 * ROWB + ks);
#pragma unroll
            for (int mi = 0; mi < 4; mi++)
#pragma unroll
                for (int nj = 0; nj < 4; nj++)
                    mma16816(acc[mi][nj][0], acc[mi][nj][1],
                             acc[mi][nj][2], acc[mi][nj][3],
                             af[mi][0], af[mi][1], af[mi][2], af[mi][3],
                             bf[nj >> 1][(nj & 1) * 2], bf[nj >> 1][(nj & 1) * 2 + 1]);
        }
    }

    const int g = lane >> 2, tq = lane & 3;
#pragma unroll
    for (int ni = 0; ni < 4; ni++) {
        int col = bn * 128 + wn * 32 + ni * 8 + tq * 2;
        float b0 = bias[col], b1 = bias[col + 1];
#pragma unroll
        for (int mi = 0; mi < 4; mi++) {
            int row = bm * 128 + wm * 64 + mi * 16 + g;
            *(float2*)&C[(size_t)row * N + col] =
                make_float2(acc[mi][ni][0] + b0, acc[mi][ni][1] + b1);
            *(float2*)&C[(size_t)(row + 8) * N + col] =
                make_float2(acc[mi][ni][2] + b0, acc[mi][ni][3] + b1);
        }
    }
}

// ---------------- persistent RNN recurrence (incremental-stage flags) -------
// 128 CTAs x 256 threads. CTA owns 8 U-rows (registers), produces 64 values
// per step (8 rows x 8 batches), stored CONTIGUOUSLY in g_h2[buf][cta][64]
// (idx = batch*8 + rowLocal). 256 pollers (2 per producer) each wait on one
// flag then immediately stage that producer's 256B into hsm — staging of
// early producers overlaps waiting for stragglers.
__global__ __launch_bounds__(256)
void rnn_recurrence_kernel(const float* __restrict__ Wx,
                           const float* __restrict__ U,
                           const float* __restrict__ bU,
                           __nv_bfloat16* __restrict__ hsb) {
    __shared__ float hsm[8][1024];

    const int tid = threadIdx.x;
    const int lane = tid & 31, w = tid >> 5;
    const int rb = blockIdx.x * 8;
    const int r0 = rb + (w & 3) * 2;      // first of this warp's 2 rows
    const int bbase = (w >> 2) * 4;       // first of this warp's 4 batches

    // staging assignment: 2 threads per producer
    const int pc = tid >> 1;              // producer CTA id (0..127)
    const int ph = tid & 1;               // half (batches 0-3 or 4-7)

    // hoist 2 rows of U into registers (64 floats)
    float4 u0[8], u1[8];
#pragma unroll
    for (int i = 0; i < 8; i++) {
        u0[i] = *(const float4*)(U + (size_t)r0 * Dd + lane * 4 + i * 128);
        u1[i] = *(const float4*)(U + (size_t)(r0 + 1) * Dd + lane * 4 + i * 128);
    }
    // per-output-lane constants (lanes 0..7 produce outputs)
    const int rowLocal = (w & 3) * 2 + (lane >> 2);
    const int orow = rb + rowLocal;
    const int obat = bbase + (lane & 3);
    const float bUv = (lane < 8) ? __ldg(&bU[orow]) : 0.f;

    for (int t = 0; t < Tt; t++) {
        // prefetch Wx for this step's outputs (lanes 0..7)
        float wxv = 0.f;
        if (lane < 8)
            wxv = __ldg(&Wx[((size_t)obat * Tt + t) * Dd + orow]);

        // incremental stage: wait for my producer, then copy its 32 floats
        if (t > 0) {
            while (ld_acquire(&g_flags[pc * 8]) < (unsigned)t) { }
        }
        {
            const float4* src = (const float4*)&g_h2[t & 1][pc][ph * 32];
            float4 v0 = __ldcg(src + 0), v1 = __ldcg(src + 1);
            float4 v2 = __ldcg(src + 2), v3 = __ldcg(src + 3);
            float4 v4 = __ldcg(src + 4), v5 = __ldcg(src + 5);
            float4 v6 = __ldcg(src + 6), v7 = __ldcg(src + 7);
            // idx = b*8 + r ; b = ph*4 + j ; dest hsm[b][pc*8 .. +8]
            *(float4*)&hsm[ph * 4 + 0][pc * 8]     = v0;
            *(float4*)&hsm[ph * 4 + 0][pc * 8 + 4] = v1;
            *(float4*)&hsm[ph * 4 + 1][pc * 8]     = v2;
            *(float4*)&hsm[ph * 4 + 1][pc * 8 + 4] = v3;
            *(float4*)&hsm[ph * 4 + 2][pc * 8]     = v4;
            *(float4*)&hsm[ph * 4 + 2][pc * 8 + 4] = v5;
            *(float4*)&hsm[ph * 4 + 3][pc * 8]     = v6;
            *(float4*)&hsm[ph * 4 + 3][pc * 8 + 4] = v7;
        }
        __syncthreads();

        float acc[2][4];
#pragma unroll
        for (int r = 0; r < 2; r++)
#pragma unroll
            for (int b = 0; b < 4; b++) acc[r][b] = 0.f;

#pragma unroll
        for (int i = 0; i < 8; i++) {
            const int k0 = lane * 4 + i * 128;
#pragma unroll
            for (int b = 0; b < 4; b++) {
                float4 h4 = *(const float4*)&hsm[bbase + b][k0];
                acc[0][b] += u0[i].x * h4.x + u0[i].y * h4.y +
                             u0[i].z * h4.z + u0[i].w * h4.w;
                acc[1][b] += u1[i].x * h4.x + u1[i].y * h4.y +
                             u1[i].z * h4.z + u1[i].w * h4.w;
            }
        }

        // butterfly-reduce 8 outputs; output j -> lane j (j = rr*4 + bb)
        float myval = 0.f;
#pragma unroll
        for (int j = 0; j < 8; j++) {
            float v = acc[j >> 2][j & 3];
            v += __shfl_xor_sync(0xffffffffu, v, 16);
            v += __shfl_xor_sync(0xffffffffu, v, 8);
            v += __shfl_xor_sync(0xffffffffu, v, 4);
            v += __shfl_xor_sync(0xffffffffu, v, 2);
            v += __shfl_xor_sync(0xffffffffu, v, 1);
            if (lane == j) myval = v;
        }

        float hn = 0.f;
        if (lane < 8) {
            hn = tanhf(myval + wxv + bUv);
            // contiguous producer-major store: idx = batch*8 + rowLocal
            __stcg(&g_h2[(t + 1) & 1][blockIdx.x][obat * 8 + rowLocal], hn);
        }
        __syncthreads();                         // all h stores done (cta scope)
        if (tid == 0)
            st_release(&g_flags[blockIdx.x * 8], (unsigned)(t + 1));
        // hsb store off the critical path (consumed by the later GEMM only)
        if (lane < 8)
            hsb[((size_t)obat * Tt + t) * Dd + orow] = __float2bfloat16(hn);
    }
}

// ---------------- fused log-softmax (SMEM-resident row) ---------------------
#define LSM_SMEM (Vv * 4)   // 128000 bytes

__global__ __launch_bounds__(256)
void logsoftmax_kernel(float* __restrict__ C) {
    extern __shared__ float rowbuf[];
    __shared__ float red[256];
    const int row = blockIdx.x, tid = threadIdx.x;
    float4* p4 = (float4*)(C + (size_t)row * Vv);
    float4* r4 = (float4*)rowbuf;

    float m = -1e30f;
    for (int i = tid; i < Vv / 4; i += 256) {
        float4 v = p4[i];
        r4[i] = v;
        m = fmaxf(m, fmaxf(fmaxf(v.x, v.y), fmaxf(v.z, v.w)));
    }
    red[tid] = m; __syncthreads();
    for (int s = 128; s > 0; s >>= 1) {
        if (tid < s) red[tid] = fmaxf(red[tid], red[tid + s]);
        __syncthreads();
    }
    m = red[0]; __syncthreads();

    float sum = 0.f;
    for (int i = tid; i < Vv / 4; i += 256) {
        float4 v = r4[i];
        sum += expf(v.x - m) + expf(v.y - m) + expf(v.z - m) + expf(v.w - m);
    }
    red[tid] = sum; __syncthreads();
    for (int s = 128; s > 0; s >>= 1) {
        if (tid < s) red[tid] += red[tid + s];
        __syncthreads();
    }
    float lse = m + logf(red[0]);
    __syncthreads();

    for (int i = tid; i < Vv / 4; i += 256) {
        float4 v = r4[i];
        v.x -= lse; v.y -= lse; v.z -= lse; v.w -= lse;
        p4[i] = v;
    }
}

// ---------------- launcher ---------------------------------------------------
extern "C" void kernel_launch(void* const* d_in, const int* in_sizes, int n_in,
                              void* d_out, int out_size) {
    const int*   idx  = (const int*)d_in[0];
    const float* E    = (const float*)d_in[1];
    const float* W    = (const float*)d_in[2];
    const float* bW   = (const float*)d_in[3];
    const float* U    = (const float*)d_in[4];
    const float* bU   = (const float*)d_in[5];
    const float* Wout = (const float*)d_in[6];
    const float* bout = (const float*)d_in[7];
    float* out = (float*)d_out;

    void* p;
    cudaGetSymbolAddress(&p, g_Xb);    __nv_bfloat16* Xb    = (__nv_bfloat16*)p;
    cudaGetSymbolAddress(&p, g_Wb);    __nv_bfloat16* Wb    = (__nv_bfloat16*)p;
    cudaGetSymbolAddress(&p, g_Woutb); __nv_bfloat16* Woutb = (__nv_bfloat16*)p;
    cudaGetSymbolAddress(&p, g_Wx);    float*         Wx    = (float*)p;
    cudaGetSymbolAddress(&p, g_hsb);   __nv_bfloat16* hsb   = (__nv_bfloat16*)p;

    cudaFuncSetAttribute(gemm_bf16_kernel,
                         cudaFuncAttributeMaxDynamicSharedMemorySize, GEMM_SMEM);
    cudaFuncSetAttribute(logsoftmax_kernel,
                         cudaFuncAttributeMaxDynamicSharedMemorySize, LSM_SMEM);

    // weight conversions
    f32_to_bf16_kernel<<<512, 256>>>((const float4*)W,
                                     (__nv_bfloat162*)Wb, (Dd * Dd) / 4);
    f32_to_bf16_kernel<<<4096, 256>>>((const float4*)Wout,
                                      (__nv_bfloat162*)Woutb, (Vv * Dd) / 4);
    // embedding gather -> bf16 ; reset rnn state
    gather_embed_kernel<<<Mrows, 128>>>(idx, E, Xb);
    rnn_reset_kernel<<<32, 256>>>();

    // input projection: Wx = Xb * Wb^T + bW   [2048 x 1024]
    dim3 g1(Mrows / 128, Dd / 128);
    gemm_bf16_kernel<<<g1, 256, GEMM_SMEM>>>(Xb, Wb, bW, Wx, Mrows, Dd, Dd);

    // recurrence (persistent, per-producer flag + incremental staging)
    rnn_recurrence_kernel<<<RNN_CTAS, 256>>>(Wx, U, bU, hsb);

    // output projection: logits = hsb * Woutb^T + bout   [2048 x 32000]
    dim3 g3(Mrows / 128, Vv / 128);
    gemm_bf16_kernel<<<g3, 256, GEMM_SMEM>>>(hsb, Woutb, bout, out, Mrows, Vv, Dd);

    // fused log_softmax
    logsoftmax_kernel<<<Mrows, 256, LSM_SMEM>>>(out);
}

// round 16
// speedup vs baseline: 1.2202x; 1.2202x over previous
#include <cuda_runtime.h>
#include <cuda_bf16.h>
#include <math.h>
#include <stdint.h>

// Problem dims (fixed)
#define Vv 32000
#define Dd 1024
#define Bb 8
#define Tt 256
#define Mrows (Bb * Tt)   // 2048

// ---------------- scratch (static device globals; allocation-free) ----------
__device__ __nv_bfloat16 g_Xb[Mrows * Dd];
__device__ __nv_bfloat16 g_Wb[Dd * Dd];
__device__ __nv_bfloat16 g_Woutb[(size_t)Vv * Dd];
__device__ float g_Wx[Mrows * Dd];
__device__ __nv_bfloat16 g_hsb[Mrows * Dd];       // rows in [t][b] order!
__device__ float g_h[2][Bb * Dd];

#define RNN_CTAS 128
__device__ unsigned g_flags[RNN_CTAS * 8];   // 32B stride per flag
__device__ unsigned g_ticket;

// ---------------- PTX helpers ----------------------------------------------
__device__ __forceinline__ uint32_t smem_u32(const void* p) {
    uint32_t a;
    asm("{ .reg .u64 t; cvta.to.shared.u64 t, %1; cvt.u32.u64 %0, t; }"
        : "=r"(a) : "l"(p));
    return a;
}

__device__ __forceinline__ void cp_async16(uint32_t dst, const void* src) {
    asm volatile("cp.async.cg.shared.global [%0], [%1], 16;" :: "r"(dst), "l"(src));
}
#define CP_COMMIT() asm volatile("cp.async.commit_group;" ::: "memory")
#define CP_WAIT(n)  asm volatile("cp.async.wait_group %0;" :: "n"(n) : "memory")

__device__ __forceinline__ void ldsm_x4(uint32_t& r0, uint32_t& r1,
                                        uint32_t& r2, uint32_t& r3, uint32_t addr) {
    asm volatile("ldmatrix.sync.aligned.m8n8.x4.shared.b16 {%0,%1,%2,%3}, [%4];"
                 : "=r"(r0), "=r"(r1), "=r"(r2), "=r"(r3) : "r"(addr));
}

__device__ __forceinline__ void mma16816(float& c0, float& c1, float& c2, float& c3,
                                         uint32_t a0, uint32_t a1, uint32_t a2, uint32_t a3,
                                         uint32_t b0, uint32_t b1) {
    asm volatile(
        "mma.sync.aligned.m16n8k16.row.col.f32.bf16.bf16.f32 "
        "{%0,%1,%2,%3}, {%4,%5,%6,%7}, {%8,%9}, {%0,%1,%2,%3};\n"
        : "+f"(c0), "+f"(c1), "+f"(c2), "+f"(c3)
        : "r"(a0), "r"(a1), "r"(a2), "r"(a3), "r"(b0), "r"(b1));
}

__device__ __forceinline__ unsigned ld_acquire(const unsigned* p) {
    unsigned v;
    asm volatile("ld.global.acquire.gpu.b32 %0, [%1];" : "=r"(v) : "l"(p) : "memory");
    return v;
}
__device__ __forceinline__ void st_release(unsigned* p, unsigned v) {
    asm volatile("st.global.release.gpu.b32 [%0], %1;" :: "l"(p), "r"(v) : "memory");
}

// ---------------- small helpers --------------------------------------------
__global__ void f32_to_bf16_kernel(const float4* __restrict__ src,
                                   __nv_bfloat162* __restrict__ dst, int n4) {
    for (int i = blockIdx.x * blockDim.x + threadIdx.x; i < n4;
         i += gridDim.x * blockDim.x) {
        float4 v = src[i];
        dst[2 * i]     = __floats2bfloat162_rn(v.x, v.y);
        dst[2 * i + 1] = __floats2bfloat162_rn(v.z, v.w);
    }
}

__global__ void gather_embed_kernel(const int* __restrict__ idx,
                                    const float* __restrict__ E,
                                    __nv_bfloat16* __restrict__ Xb) {
    int row = blockIdx.x;
    int v = idx[row];
    const float4* src = (const float4*)(E + (size_t)v * Dd);
    __nv_bfloat162* dst = (__nv_bfloat162*)(Xb + (size_t)row * Dd);
    for (int i = threadIdx.x; i < Dd / 4; i += blockDim.x) {
        float4 a = src[i];
        dst[2 * i]     = __floats2bfloat162_rn(a.x, a.y);
        dst[2 * i + 1] = __floats2bfloat162_rn(a.z, a.w);
    }
}

__global__ void rnn_reset_kernel() {
    int i = blockIdx.x * blockDim.x + threadIdx.x;
    if (i < Bb * Dd) g_h[0][i] = 0.f;
    if (i < RNN_CTAS) g_flags[i * 8] = 0u;
    if (i == 0) g_ticket = 0u;
}

// ---------------- pipelined HMMA GEMM (standalone, used for Wx) -------------
#define ROWB 80
#define A_BYTES (128 * ROWB)
#define STG (2 * A_BYTES)
#define S_ST 3
#define GEMM_SMEM (S_ST * STG + 128)

__device__ __forceinline__ void load_stage(const __nv_bfloat16* Ag,
                                           const __nv_bfloat16* Bg, int K,
                                           int kt, uint32_t base, int tid) {
    const int kbase = kt * 32;
#pragma unroll
    for (int i = 0; i < 2; i++) {
        int id = tid + i * 256;
        int row = id >> 2, seg = id & 3;
        uint32_t soff = row * ROWB + seg * 16;
        cp_async16(base + soff, Ag + (size_t)row * K + kbase + seg * 8);
        cp_async16(base + A_BYTES + soff, Bg + (size_t)row * K + kbase + seg * 8);
    }
}

__global__ __launch_bounds__(256, 2)
void gemm_bf16_kernel(const __nv_bfloat16* __restrict__ A,
                      const __nv_bfloat16* __restrict__ Bm,
                      const float* __restrict__ bias,
                      float* __restrict__ C, int M, int N, int K) {
    extern __shared__ char dsm[];
    uint32_t sb = (smem_u32(dsm) + 127) & ~127u;

    const int tid = threadIdx.x;
    const int warp = tid >> 5, lane = tid & 31;
    const int wm = warp >> 2, wn = warp & 3;
    const int bm = blockIdx.x, bn = blockIdx.y;
    const int NT = K / 32;

    const uint32_t aLane = (uint32_t)((lane & 15) * ROWB + ((lane >> 4) << 4));
    const uint32_t bLane = (uint32_t)((((lane >> 4) << 3) + (lane & 7)) * ROWB +
                                      (((lane >> 3) & 1) << 4));

    float acc[4][4][4];
#pragma unroll
    for (int mi = 0; mi < 4; mi++)
#pragma unroll
        for (int ni = 0; ni < 4; ni++)
#pragma unroll
            for (int q = 0; q < 4; q++) acc[mi][ni][q] = 0.f;

    const __nv_bfloat16* Ag = A + (size_t)(bm * 128) * K;
    const __nv_bfloat16* Bg = Bm + (size_t)(bn * 128) * K;

    load_stage(Ag, Bg, K, 0, sb, tid);
    CP_COMMIT();
    load_stage(Ag, Bg, K, 1, sb + STG, tid);
    CP_COMMIT();

    for (int kt = 0; kt < NT; kt++) {
        CP_WAIT(1);
        __syncthreads();

        const int ktn = kt + 2;
        if (ktn < NT)
            load_stage(Ag, Bg, K, ktn, sb + (ktn % S_ST) * STG, tid);
        CP_COMMIT();

        const uint32_t stage = sb + (kt % S_ST) * STG;
        const uint32_t aBase = stage + (wm * 64) * ROWB + aLane;
        const uint32_t bBase = stage + A_BYTES + (wn * 32) * ROWB + bLane;

#pragma unroll
        for (int ks = 0; ks < 64; ks += 32) {
            uint32_t af[4][4], bf[2][4];
#pragma unroll
            for (int mi = 0; mi < 4; mi++)
                ldsm_x4(af[mi][0], af[mi][1], af[mi][2], af[mi][3],
                        aBase + mi * 16 * ROWB + ks);
#pragma unroll
            for (int nb = 0; nb < 2; nb++)
                ldsm_x4(bf[nb][0], bf[nb][1], bf[nb][2], bf[nb][3],
                        bBase + nb * 16 * ROWB + ks);
#pragma unroll
            for (int mi = 0; mi < 4; mi++)
#pragma unroll
                for (int nj = 0; nj < 4; nj++)
                    mma16816(acc[mi][nj][0], acc[mi][nj][1],
                             acc[mi][nj][2], acc[mi][nj][3],
                             af[mi][0], af[mi][1], af[mi][2], af[mi][3],
                             bf[nj >> 1][(nj & 1) * 2], bf[nj >> 1][(nj & 1) * 2 + 1]);
        }
    }

    const int g = lane >> 2, tq = lane & 3;
#pragma unroll
    for (int ni = 0; ni < 4; ni++) {
        int col = bn * 128 + wn * 32 + ni * 8 + tq * 2;
        float b0 = bias[col], b1 = bias[col + 1];
#pragma unroll
        for (int mi = 0; mi < 4; mi++) {
            int row = bm * 128 + wm * 64 + mi * 16 + g;
            *(float2*)&C[(size_t)row * N + col] =
                make_float2(acc[mi][ni][0] + b0, acc[mi][ni][1] + b1);
            *(float2*)&C[(size_t)(row + 8) * N + col] =
                make_float2(acc[mi][ni][2] + b0, acc[mi][ni][3] + b1);
        }
    }
}

// ---------------- fused recurrence + output projection ----------------------
// grid = 256 CTAs x 256 threads (2/SM, fully resident -> no deadlock).
// CTAs 0..127: R7-style flag-handshake recurrence, then join GEMM tile pool.
// CTAs 128..255: GEMM tiles via atomic ticket; tile (bm,bn) waits until all
// 128 producer flags >= (bm+1)*16 (hsb rows are in [t][b] order, so a 128-row
// tile spans timesteps [bm*16, bm*16+16)).
#define TILE_TOTAL (16 * 250)

__device__ __forceinline__ void rnn_role(const float* __restrict__ Wx,
                                         const float* __restrict__ U,
                                         const float* __restrict__ bU,
                                         __nv_bfloat16* __restrict__ hsb,
                                         float (*hsm)[1024]) {
    const int tid = threadIdx.x;
    const int lane = tid & 31, w = tid >> 5;
    const int rb = blockIdx.x * 8;
    const int r0 = rb + (w & 3) * 2;
    const int bbase = (w >> 2) * 4;

    float4 u0[8], u1[8];
#pragma unroll
    for (int i = 0; i < 8; i++) {
        u0[i] = *(const float4*)(U + (size_t)r0 * Dd + lane * 4 + i * 128);
        u1[i] = *(const float4*)(U + (size_t)(r0 + 1) * Dd + lane * 4 + i * 128);
    }
    const int rowLocal = (w & 3) * 2 + (lane >> 2);
    const int orow = rb + rowLocal;
    const int obat = bbase + (lane & 3);
    const float bUv = (lane < 8) ? __ldg(&bU[orow]) : 0.f;

    for (int t = 0; t < Tt; t++) {
        float wxv = 0.f;
        if (lane < 8)
            wxv = __ldg(&Wx[((size_t)obat * Tt + t) * Dd + orow]);

        if (t > 0 && tid < RNN_CTAS) {
            while (ld_acquire(&g_flags[tid * 8]) < (unsigned)t) { }
        }
        __syncthreads();

        const float4* hc = (const float4*)g_h[t & 1];
        for (int i = tid; i < 2048; i += 256) {
            float4 v = __ldcg(hc + i);
            *(float4*)&hsm[i >> 8][(i & 255) * 4] = v;
        }
        __syncthreads();

        float acc[2][4];
#pragma unroll
        for (int r = 0; r < 2; r++)
#pragma unroll
            for (int b = 0; b < 4; b++) acc[r][b] = 0.f;

#pragma unroll
        for (int i = 0; i < 8; i++) {
            const int k0 = lane * 4 + i * 128;
#pragma unroll
            for (int b = 0; b < 4; b++) {
                float4 h4 = *(const float4*)&hsm[bbase + b][k0];
                acc[0][b] += u0[i].x * h4.x + u0[i].y * h4.y +
                             u0[i].z * h4.z + u0[i].w * h4.w;
                acc[1][b] += u1[i].x * h4.x + u1[i].y * h4.y +
                             u1[i].z * h4.z + u1[i].w * h4.w;
            }
        }

        float myval = 0.f;
#pragma unroll
        for (int j = 0; j < 8; j++) {
            float v = acc[j >> 2][j & 3];
            v += __shfl_xor_sync(0xffffffffu, v, 16);
            v += __shfl_xor_sync(0xffffffffu, v, 8);
            v += __shfl_xor_sync(0xffffffffu, v, 4);
            v += __shfl_xor_sync(0xffffffffu, v, 2);
            v += __shfl_xor_sync(0xffffffffu, v, 1);
            if (lane == j) myval = v;
        }

        if (lane < 8) {
            float hn = tanhf(myval + wxv + bUv);
            __stcg(&g_h[(t + 1) & 1][obat * Dd + orow], hn);
            // [t][b]-ordered row for the overlapped GEMM
            hsb[((size_t)(t * 8 + obat)) * Dd + orow] = __float2bfloat16(hn);
            __threadfence();
        }
        __syncthreads();
        if (tid == 0)
            st_release(&g_flags[blockIdx.x * 8], (unsigned)(t + 1));
    }
}

__global__ __launch_bounds__(256, 2)
void fused_rnn_gemm_kernel(const float* __restrict__ Wx,
                           const float* __restrict__ U,
                           const float* __restrict__ bU,
                           __nv_bfloat16* __restrict__ hsb,
                           const __nv_bfloat16* __restrict__ Wout,
                           const float* __restrict__ bias,
                           float* __restrict__ C) {
    __shared__ float hsm[8][1024];
    __shared__ unsigned s_ticket;
    extern __shared__ char dsm[];
    uint32_t sb = (smem_u32(dsm) + 127) & ~127u;

    if (blockIdx.x < RNN_CTAS)
        rnn_role(Wx, U, bU, hsb, hsm);

    // ---- GEMM tile pool ----
    const int tid = threadIdx.x;
    const int warp = tid >> 5, lane = tid & 31;
    const int wm = warp >> 2, wn = warp & 3;
    const uint32_t aLane = (uint32_t)((lane & 15) * ROWB + ((lane >> 4) << 4));
    const uint32_t bLane = (uint32_t)((((lane >> 4) << 3) + (lane & 7)) * ROWB +
                                      (((lane >> 3) & 1) << 4));

    for (;;) {
        __syncthreads();
        if (tid == 0) s_ticket = atomicAdd(&g_ticket, 1u);
        __syncthreads();
        const unsigned tk = s_ticket;
        if (tk >= TILE_TOTAL) break;
        const int bm = tk / 250, bn = tk % 250;

        // wait until timesteps [bm*16, bm*16+16) are produced by ALL CTAs
        const unsigned tneed = (unsigned)((bm + 1) * 16);
        if (tid < RNN_CTAS) {
            while (ld_acquire(&g_flags[tid * 8]) < tneed) __nanosleep(256);
        }
        __syncthreads();

        float acc[4][4][4];
#pragma unroll
        for (int mi = 0; mi < 4; mi++)
#pragma unroll
            for (int ni = 0; ni < 4; ni++)
#pragma unroll
                for (int q = 0; q < 4; q++) acc[mi][ni][q] = 0.f;

        const __nv_bfloat16* Ag = hsb + (size_t)(bm * 128) * Dd;
        const __nv_bfloat16* Bg = Wout + (size_t)(bn * 128) * Dd;

        CP_WAIT(0);
        load_stage(Ag, Bg, Dd, 0, sb, tid);
        CP_COMMIT();
        load_stage(Ag, Bg, Dd, 1, sb + STG, tid);
        CP_COMMIT();

#pragma unroll 1
        for (int kt = 0; kt < 32; kt++) {
            CP_WAIT(1);
            __syncthreads();

            const int ktn = kt + 2;
            if (ktn < 32)
                load_stage(Ag, Bg, Dd, ktn, sb + (ktn % S_ST) * STG, tid);
            CP_COMMIT();

            const uint32_t stage = sb + (kt % S_ST) * STG;
            const uint32_t aBase = stage + (wm * 64) * ROWB + aLane;
            const uint32_t bBase = stage + A_BYTES + (wn * 32) * ROWB + bLane;

#pragma unroll
            for (int ks = 0; ks < 64; ks += 32) {
                uint32_t af[4][4], bf[2][4];
#pragma unroll
                for (int mi = 0; mi < 4; mi++)
                    ldsm_x4(af[mi][0], af[mi][1], af[mi][2], af[mi][3],
                            aBase + mi * 16 * ROWB + ks);
#pragma unroll
                for (int nb = 0; nb < 2; nb++)
                    ldsm_x4(bf[nb][0], bf[nb][1], bf[nb][2], bf[nb][3],
                            bBase + nb * 16 * ROWB + ks);
#pragma unroll
                for (int mi = 0; mi < 4; mi++)
#pragma unroll
                    for (int nj = 0; nj < 4; nj++)
                        mma16816(acc[mi][nj][0], acc[mi][nj][1],
                                 acc[mi][nj][2], acc[mi][nj][3],
                                 af[mi][0], af[mi][1], af[mi][2], af[mi][3],
                                 bf[nj >> 1][(nj & 1) * 2],
                                 bf[nj >> 1][(nj & 1) * 2 + 1]);
            }
        }

        // epilogue: remap rows [t][b] -> output rows [b][t]
        const int g = lane >> 2, tq = lane & 3;
#pragma unroll
        for (int ni = 0; ni < 4; ni++) {
            int col = bn * 128 + wn * 32 + ni * 8 + tq * 2;
            float b0 = __ldg(&bias[col]), b1 = __ldg(&bias[col + 1]);
#pragma unroll
            for (int mi = 0; mi < 4; mi++) {
                int rs = bm * 128 + wm * 64 + mi * 16 + g;
                int orow0 = (rs & 7) * Tt + (rs >> 3);
                int rs2 = rs + 8;
                int orow1 = (rs2 & 7) * Tt + (rs2 >> 3);
                *(float2*)&C[(size_t)orow0 * Vv + col] =
                    make_float2(acc[mi][ni][0] + b0, acc[mi][ni][1] + b1);
                *(float2*)&C[(size_t)orow1 * Vv + col] =
                    make_float2(acc[mi][ni][2] + b0, acc[mi][ni][3] + b1);
            }
        }
    }
}

// ---------------- fused log-softmax (SMEM-resident row) ---------------------
#define LSM_SMEM (Vv * 4)   // 128000 bytes

__global__ __launch_bounds__(256)
void logsoftmax_kernel(float* __restrict__ C) {
    extern __shared__ float rowbuf[];
    __shared__ float red[256];
    const int row = blockIdx.x, tid = threadIdx.x;
    float4* p4 = (float4*)(C + (size_t)row * Vv);
    float4* r4 = (float4*)rowbuf;

    float m = -1e30f;
    for (int i = tid; i < Vv / 4; i += 256) {
        float4 v = p4[i];
        r4[i] = v;
        m = fmaxf(m, fmaxf(fmaxf(v.x, v.y), fmaxf(v.z, v.w)));
    }
    red[tid] = m; __syncthreads();
    for (int s = 128; s > 0; s >>= 1) {
        if (tid < s) red[tid] = fmaxf(red[tid], red[tid + s]);
        __syncthreads();
    }
    m = red[0]; __syncthreads();

    float sum = 0.f;
    for (int i = tid; i < Vv / 4; i += 256) {
        float4 v = r4[i];
        sum += expf(v.x - m) + expf(v.y - m) + expf(v.z - m) + expf(v.w - m);
    }
    red[tid] = sum; __syncthreads();
    for (int s = 128; s > 0; s >>= 1) {
        if (tid < s) red[tid] += red[tid + s];
        __syncthreads();
    }
    float lse = m + logf(red[0]);
    __syncthreads();

    for (int i = tid; i < Vv / 4; i += 256) {
        float4 v = r4[i];
        v.x -= lse; v.y -= lse; v.z -= lse; v.w -= lse;
        p4[i] = v;
    }
}

// ---------------- launcher ---------------------------------------------------
extern "C" void kernel_launch(void* const* d_in, const int* in_sizes, int n_in,
                              void* d_out, int out_size) {
    const int*   idx  = (const int*)d_in[0];
    const float* E    = (const float*)d_in[1];
    const float* W    = (const float*)d_in[2];
    const float* bW   = (const float*)d_in[3];
    const float* U    = (const float*)d_in[4];
    const float* bU   = (const float*)d_in[5];
    const float* Wout = (const float*)d_in[6];
    const float* bout = (const float*)d_in[7];
    float* out = (float*)d_out;

    void* p;
    cudaGetSymbolAddress(&p, g_Xb);    __nv_bfloat16* Xb    = (__nv_bfloat16*)p;
    cudaGetSymbolAddress(&p, g_Wb);    __nv_bfloat16* Wb    = (__nv_bfloat16*)p;
    cudaGetSymbolAddress(&p, g_Woutb); __nv_bfloat16* Woutb = (__nv_bfloat16*)p;
    cudaGetSymbolAddress(&p, g_Wx);    float*         Wx    = (float*)p;
    cudaGetSymbolAddress(&p, g_hsb);   __nv_bfloat16* hsb   = (__nv_bfloat16*)p;

    cudaFuncSetAttribute(gemm_bf16_kernel,
                         cudaFuncAttributeMaxDynamicSharedMemorySize, GEMM_SMEM);
    cudaFuncSetAttribute(fused_rnn_gemm_kernel,
                         cudaFuncAttributeMaxDynamicSharedMemorySize, GEMM_SMEM);
    cudaFuncSetAttribute(logsoftmax_kernel,
                         cudaFuncAttributeMaxDynamicSharedMemorySize, LSM_SMEM);

    // weight conversions + gather + state reset
    f32_to_bf16_kernel<<<512, 256>>>((const float4*)W,
                                     (__nv_bfloat162*)Wb, (Dd * Dd) / 4);
    f32_to_bf16_kernel<<<4096, 256>>>((const float4*)Wout,
                                      (__nv_bfloat162*)Woutb, (Vv * Dd) / 4);
    gather_embed_kernel<<<Mrows, 128>>>(idx, E, Xb);
    rnn_reset_kernel<<<32, 256>>>();

    // input projection: Wx = Xb * Wb^T + bW   [2048 x 1024]
    dim3 g1(Mrows / 128, Dd / 128);
    gemm_bf16_kernel<<<g1, 256, GEMM_SMEM>>>(Xb, Wb, bW, Wx, Mrows, Dd, Dd);

    // fused recurrence + overlapped output projection
    fused_rnn_gemm_kernel<<<256, 256, GEMM_SMEM>>>(Wx, U, bU, hsb,
                                                   Woutb, bout, out);

    // fused log_softmax
    logsoftmax_kernel<<<Mrows, 256, LSM_SMEM>>>(out);
}

// round 17
// speedup vs baseline: 1.4760x; 1.2097x over previous
#include <cuda_runtime.h>
#include <cuda_bf16.h>
#include <math.h>
#include <stdint.h>

// Problem dims (fixed)
#define Vv 32000
#define Dd 1024
#define Bb 8
#define Tt 256
#define Mrows (Bb * Tt)   // 2048

// ---------------- scratch (static device globals; allocation-free) ----------
__device__ __nv_bfloat16 g_Xb[Mrows * Dd];
__device__ __nv_bfloat16 g_Wb[Dd * Dd];
__device__ __nv_bfloat16 g_Ub[Dd * Dd];
__device__ __nv_bfloat16 g_Woutb[(size_t)Vv * Dd];
__device__ float g_Wx[Mrows * Dd];
__device__ __nv_bfloat16 g_hsb[Mrows * Dd];       // rows in [t][b] order!

#define RNN_CTAS 128
// h state: [buf][group(4)][cta(32)][batchInPair(2)*32 rows] (256B per CTA blk)
__device__ float g_hp[2][4][32][64];
__device__ unsigned g_flags[RNN_CTAS * 8];   // 32B stride per flag
__device__ unsigned g_ticket;

// ---------------- PTX helpers ----------------------------------------------
__device__ __forceinline__ uint32_t smem_u32(const void* p) {
    uint32_t a;
    asm("{ .reg .u64 t; cvta.to.shared.u64 t, %1; cvt.u32.u64 %0, t; }"
        : "=r"(a) : "l"(p));
    return a;
}

__device__ __forceinline__ void cp_async16(uint32_t dst, const void* src) {
    asm volatile("cp.async.cg.shared.global [%0], [%1], 16;" :: "r"(dst), "l"(src));
}
#define CP_COMMIT() asm volatile("cp.async.commit_group;" ::: "memory")
#define CP_WAIT(n)  asm volatile("cp.async.wait_group %0;" :: "n"(n) : "memory")

__device__ __forceinline__ void ldsm_x4(uint32_t& r0, uint32_t& r1,
                                        uint32_t& r2, uint32_t& r3, uint32_t addr) {
    asm volatile("ldmatrix.sync.aligned.m8n8.x4.shared.b16 {%0,%1,%2,%3}, [%4];"
                 : "=r"(r0), "=r"(r1), "=r"(r2), "=r"(r3) : "r"(addr));
}

__device__ __forceinline__ void mma16816(float& c0, float& c1, float& c2, float& c3,
                                         uint32_t a0, uint32_t a1, uint32_t a2, uint32_t a3,
                                         uint32_t b0, uint32_t b1) {
    asm volatile(
        "mma.sync.aligned.m16n8k16.row.col.f32.bf16.bf16.f32 "
        "{%0,%1,%2,%3}, {%4,%5,%6,%7}, {%8,%9}, {%0,%1,%2,%3};\n"
        : "+f"(c0), "+f"(c1), "+f"(c2), "+f"(c3)
        : "r"(a0), "r"(a1), "r"(a2), "r"(a3), "r"(b0), "r"(b1));
}

__device__ __forceinline__ unsigned ld_acquire(const unsigned* p) {
    unsigned v;
    asm volatile("ld.global.acquire.gpu.b32 %0, [%1];" : "=r"(v) : "l"(p) : "memory");
    return v;
}
__device__ __forceinline__ void st_release(unsigned* p, unsigned v) {
    asm volatile("st.global.release.gpu.b32 [%0], %1;" :: "l"(p), "r"(v) : "memory");
}

// ---------------- small helpers --------------------------------------------
__global__ void f32_to_bf16_kernel(const float4* __restrict__ src,
                                   __nv_bfloat162* __restrict__ dst, int n4) {
    for (int i = blockIdx.x * blockDim.x + threadIdx.x; i < n4;
         i += gridDim.x * blockDim.x) {
        float4 v = src[i];
        dst[2 * i]     = __floats2bfloat162_rn(v.x, v.y);
        dst[2 * i + 1] = __floats2bfloat162_rn(v.z, v.w);
    }
}

__global__ void gather_embed_kernel(const int* __restrict__ idx,
                                    const float* __restrict__ E,
                                    __nv_bfloat16* __restrict__ Xb) {
    int row = blockIdx.x;
    int v = idx[row];
    const float4* src = (const float4*)(E + (size_t)v * Dd);
    __nv_bfloat162* dst = (__nv_bfloat162*)(Xb + (size_t)row * Dd);
    for (int i = threadIdx.x; i < Dd / 4; i += blockDim.x) {
        float4 a = src[i];
        dst[2 * i]     = __floats2bfloat162_rn(a.x, a.y);
        dst[2 * i + 1] = __floats2bfloat162_rn(a.z, a.w);
    }
}

__global__ void rnn_reset_kernel() {
    int i = blockIdx.x * blockDim.x + threadIdx.x;
    if (i < 4 * 32 * 64) ((float*)g_hp)[i] = 0.f;   // zero buffer 0
    if (i < RNN_CTAS) g_flags[i * 8] = 0u;
    if (i == 0) g_ticket = 0u;
}

// ---------------- pipelined HMMA GEMM (standalone, used for Wx) -------------
#define ROWB 80
#define A_BYTES (128 * ROWB)
#define STG (2 * A_BYTES)
#define S_ST 3
#define GEMM_SMEM (S_ST * STG + 128)

__device__ __forceinline__ void load_stage(const __nv_bfloat16* Ag,
                                           const __nv_bfloat16* Bg, int K,
                                           int kt, uint32_t base, int tid) {
    const int kbase = kt * 32;
#pragma unroll
    for (int i = 0; i < 2; i++) {
        int id = tid + i * 256;
        int row = id >> 2, seg = id & 3;
        uint32_t soff = row * ROWB + seg * 16;
        cp_async16(base + soff, Ag + (size_t)row * K + kbase + seg * 8);
        cp_async16(base + A_BYTES + soff, Bg + (size_t)row * K + kbase + seg * 8);
    }
}

__global__ __launch_bounds__(256, 2)
void gemm_bf16_kernel(const __nv_bfloat16* __restrict__ A,
                      const __nv_bfloat16* __restrict__ Bm,
                      const float* __restrict__ bias,
                      float* __restrict__ C, int M, int N, int K) {
    extern __shared__ char dsm[];
    uint32_t sb = (smem_u32(dsm) + 127) & ~127u;

    const int tid = threadIdx.x;
    const int warp = tid >> 5, lane = tid & 31;
    const int wm = warp >> 2, wn = warp & 3;
    const int bm = blockIdx.x, bn = blockIdx.y;
    const int NT = K / 32;

    const uint32_t aLane = (uint32_t)((lane & 15) * ROWB + ((lane >> 4) << 4));
    const uint32_t bLane = (uint32_t)((((lane >> 4) << 3) + (lane & 7)) * ROWB +
                                      (((lane >> 3) & 1) << 4));

    float acc[4][4][4];
#pragma unroll
    for (int mi = 0; mi < 4; mi++)
#pragma unroll
        for (int ni = 0; ni < 4; ni++)
#pragma unroll
            for (int q = 0; q < 4; q++) acc[mi][ni][q] = 0.f;

    const __nv_bfloat16* Ag = A + (size_t)(bm * 128) * K;
    const __nv_bfloat16* Bg = Bm + (size_t)(bn * 128) * K;

    load_stage(Ag, Bg, K, 0, sb, tid);
    CP_COMMIT();
    load_stage(Ag, Bg, K, 1, sb + STG, tid);
    CP_COMMIT();

    for (int kt = 0; kt < NT; kt++) {
        CP_WAIT(1);
        __syncthreads();

        const int ktn = kt + 2;
        if (ktn < NT)
            load_stage(Ag, Bg, K, ktn, sb + (ktn % S_ST) * STG, tid);
        CP_COMMIT();

        const uint32_t stage = sb + (kt % S_ST) * STG;
        const uint32_t aBase = stage + (wm * 64) * ROWB + aLane;
        const uint32_t bBase = stage + A_BYTES + (wn * 32) * ROWB + bLane;

#pragma unroll
        for (int ks = 0; ks < 64; ks += 32) {
            uint32_t af[4][4], bf[2][4];
#pragma unroll
            for (int mi = 0; mi < 4; mi++)
                ldsm_x4(af[mi][0], af[mi][1], af[mi][2], af[mi][3],
                        aBase + mi * 16 * ROWB + ks);
#pragma unroll
            for (int nb = 0; nb < 2; nb++)
                ldsm_x4(bf[nb][0], bf[nb][1], bf[nb][2], bf[nb][3],
                        bBase + nb * 16 * ROWB + ks);
#pragma unroll
            for (int mi = 0; mi < 4; mi++)
#pragma unroll
                for (int nj = 0; nj < 4; nj++)
                    mma16816(acc[mi][nj][0], acc[mi][nj][1],
                             acc[mi][nj][2], acc[mi][nj][3],
                             af[mi][0], af[mi][1], af[mi][2], af[mi][3],
                             bf[nj >> 1][(nj & 1) * 2], bf[nj >> 1][(nj & 1) * 2 + 1]);
        }
    }

    const int g = lane >> 2, tq = lane & 3;
#pragma unroll
    for (int ni = 0; ni < 4; ni++) {
        int col = bn * 128 + wn * 32 + ni * 8 + tq * 2;
        float b0 = bias[col], b1 = bias[col + 1];
#pragma unroll
        for (int mi = 0; mi < 4; mi++) {
            int row = bm * 128 + wm * 64 + mi * 16 + g;
            *(float2*)&C[(size_t)row * N + col] =
                make_float2(acc[mi][ni][0] + b0, acc[mi][ni][1] + b1);
            *(float2*)&C[(size_t)(row + 8) * N + col] =
                make_float2(acc[mi][ni][2] + b0, acc[mi][ni][3] + b1);
        }
    }
}

// ---------------- fused recurrence + output projection ----------------------
// grid = 256 CTAs x 256 threads (2/SM, all resident -> deadlock-free).
// CTAs 0..127: batch-grouped recurrence. Group p = bid>>5 owns batches
// {2p, 2p+1}; CTA i = bid&31 owns h-rows [32i, 32i+32) with its 64KB bf16
// U-slice in SMEM. Per step: poll 32 group flags, stage 8KB group h,
// SMEM FMA (U-row reused across both batches), butterfly, 256B store, release.
// CTAs 128..255: GEMM tile pool (watermark on all 128 flags), rnn CTAs join
// the pool when done.
#define TILE_TOTAL (16 * 250)
#define RNN_U_BYTES 65536                       // 32 rows x 1024 bf16 x2B
#define FUSED_SMEM (RNN_U_BYTES + 8192 + 128)   // U + hsm[2][1024] + pad

__device__ __forceinline__ void rnn_role(const float* __restrict__ Wx,
                                         const float* __restrict__ bU,
                                         __nv_bfloat16* __restrict__ hsb,
                                         char* dyn) {
    const uint4* Us = (const uint4*)dyn;        // [32 rows][128 uint4]
    float* hsm = (float*)(dyn + RNN_U_BYTES);   // [2][1024]

    const int tid = threadIdx.x;
    const int lane = tid & 31, w = tid >> 5;
    const int bid = blockIdx.x;
    const int p = bid >> 5, i = bid & 31;       // group / member

    // load U slice: global rows [i*32, i*32+32), bf16, 64KB
    {
        const uint32_t ub = smem_u32(dyn);
        const char* usrc = (const char*)(g_Ub + (size_t)(i * 32) * Dd);
        for (int c = tid; c < RNN_U_BYTES / 16; c += 256)
            cp_async16(ub + c * 16, usrc + c * 16);
        CP_COMMIT();
        CP_WAIT(0);
    }
    __syncthreads();

    // output mapping: lanes 0..7: rr = lane>>1 (row in warp), b = lane&1
    const int rl = w * 4 + (lane >> 1);         // local row 0..31
    const int orow = i * 32 + rl;               // global h row
    const int bgl = 2 * p + (lane & 1);         // global batch
    const float bUv = (lane < 8) ? __ldg(&bU[orow]) : 0.f;

    // staging assignment: thread tid stages producer isrc = tid>>3, q = tid&7
    const int isrc = tid >> 3, q = tid & 7;

    for (int t = 0; t < Tt; t++) {
        float wxv = 0.f;
        if (lane < 8)
            wxv = __ldg(&Wx[((size_t)bgl * Tt + t) * Dd + orow]);

        if (t > 0 && tid < 32) {
            while (ld_acquire(&g_flags[(p * 32 + tid) * 8]) < (unsigned)t) { }
        }
        __syncthreads();

        // stage group h: 8KB = 32 producers x 2 batches x 32 floats
        {
            const float4* src = (const float4*)&g_hp[t & 1][p][isrc][0];
            float4 f0 = __ldcg(src + q);        // batch 0 chunk
            float4 f1 = __ldcg(src + 8 + q);    // batch 1 chunk
            *(float4*)&hsm[isrc * 32 + q * 4] = f0;
            *(float4*)&hsm[1024 + isrc * 32 + q * 4] = f1;
        }
        __syncthreads();

        float acc[4][2];
#pragma unroll
        for (int r = 0; r < 4; r++) { acc[r][0] = 0.f; acc[r][1] = 0.f; }

#pragma unroll
        for (int j = 0; j < 4; j++) {
            const int k0 = lane * 8 + j * 256;
            const float4 h0a = *(const float4*)&hsm[k0];
            const float4 h0b = *(const float4*)&hsm[k0 + 4];
            const float4 h1a = *(const float4*)&hsm[1024 + k0];
            const float4 h1b = *(const float4*)&hsm[1024 + k0 + 4];
#pragma unroll
            for (int r = 0; r < 4; r++) {
                const uint4 uu = Us[(w * 4 + r) * 128 + lane + j * 32];
                const float f0 = __uint_as_float(uu.x << 16);
                const float f1 = __uint_as_float(uu.x & 0xFFFF0000u);
                const float f2 = __uint_as_float(uu.y << 16);
                const float f3 = __uint_as_float(uu.y & 0xFFFF0000u);
                const float f4 = __uint_as_float(uu.z << 16);
                const float f5 = __uint_as_float(uu.z & 0xFFFF0000u);
                const float f6 = __uint_as_float(uu.w << 16);
                const float f7 = __uint_as_float(uu.w & 0xFFFF0000u);
                acc[r][0] += f0 * h0a.x + f1 * h0a.y + f2 * h0a.z + f3 * h0a.w +
                             f4 * h0b.x + f5 * h0b.y + f6 * h0b.z + f7 * h0b.w;
                acc[r][1] += f0 * h1a.x + f1 * h1a.y + f2 * h1a.z + f3 * h1a.w +
                             f4 * h1b.x + f5 * h1b.y + f6 * h1b.z + f7 * h1b.w;
            }
        }

        // butterfly-reduce 8 outputs; output j = rr*2 + b -> lane j
        float myval = 0.f;
#pragma unroll
        for (int j = 0; j < 8; j++) {
            float v = acc[j >> 1][j & 1];
            v += __shfl_xor_sync(0xffffffffu, v, 16);
            v += __shfl_xor_sync(0xffffffffu, v, 8);
            v += __shfl_xor_sync(0xffffffffu, v, 4);
            v += __shfl_xor_sync(0xffffffffu, v, 2);
            v += __shfl_xor_sync(0xffffffffu, v, 1);
            if (lane == j) myval = v;
        }

        if (lane < 8) {
            float hn = tanhf(myval + wxv + bUv);
            // producer-major store: [b][local row]
            __stcg(&g_hp[(t + 1) & 1][p][i][(lane & 1) * 32 + rl], hn);
            // [t][b]-ordered row for the overlapped GEMM
            hsb[((size_t)(t * 8 + bgl)) * Dd + orow] = __float2bfloat16(hn);
            __threadfence();
        }
        __syncthreads();
        if (tid == 0)
            st_release(&g_flags[bid * 8], (unsigned)(t + 1));
    }
}

__global__ __launch_bounds__(256, 2)
void fused_rnn_gemm_kernel(const float* __restrict__ Wx,
                           const float* __restrict__ bU,
                           __nv_bfloat16* __restrict__ hsb,
                           const __nv_bfloat16* __restrict__ Wout,
                           const float* __restrict__ bias,
                           float* __restrict__ C) {
    __shared__ unsigned s_ticket;
    extern __shared__ char dsm[];
    uint32_t sb = (smem_u32(dsm) + 127) & ~127u;

    if (blockIdx.x < RNN_CTAS)
        rnn_role(Wx, bU, hsb, dsm);

    // ---- GEMM tile pool ----
    const int tid = threadIdx.x;
    const int warp = tid >> 5, lane = tid & 31;
    const int wm = warp >> 2, wn = warp & 3;
    const uint32_t aLane = (uint32_t)((lane & 15) * ROWB + ((lane >> 4) << 4));
    const uint32_t bLane = (uint32_t)((((lane >> 4) << 3) + (lane & 7)) * ROWB +
                                      (((lane >> 3) & 1) << 4));

    for (;;) {
        __syncthreads();
        if (tid == 0) s_ticket = atomicAdd(&g_ticket, 1u);
        __syncthreads();
        const unsigned tk = s_ticket;
        if (tk >= TILE_TOTAL) break;
        const int bm = tk / 250, bn = tk % 250;

        // wait until timesteps [bm*16, bm*16+16) are produced by ALL CTAs
        const unsigned tneed = (unsigned)((bm + 1) * 16);
        if (tid < RNN_CTAS) {
            while (ld_acquire(&g_flags[tid * 8]) < tneed) __nanosleep(256);
        }
        __syncthreads();

        float acc[4][4][4];
#pragma unroll
        for (int mi = 0; mi < 4; mi++)
#pragma unroll
            for (int ni = 0; ni < 4; ni++)
#pragma unroll
                for (int q = 0; q < 4; q++) acc[mi][ni][q] = 0.f;

        const __nv_bfloat16* Ag = hsb + (size_t)(bm * 128) * Dd;
        const __nv_bfloat16* Bg = Wout + (size_t)(bn * 128) * Dd;

        CP_WAIT(0);
        load_stage(Ag, Bg, Dd, 0, sb, tid);
        CP_COMMIT();
        load_stage(Ag, Bg, Dd, 1, sb + STG, tid);
        CP_COMMIT();

#pragma unroll 1
        for (int kt = 0; kt < 32; kt++) {
            CP_WAIT(1);
            __syncthreads();

            const int ktn = kt + 2;
            if (ktn < 32)
                load_stage(Ag, Bg, Dd, ktn, sb + (ktn % S_ST) * STG, tid);
            CP_COMMIT();

            const uint32_t stage = sb + (kt % S_ST) * STG;
            const uint32_t aBase = stage + (wm * 64) * ROWB + aLane;
            const uint32_t bBase = stage + A_BYTES + (wn * 32) * ROWB + bLane;

#pragma unroll
            for (int ks = 0; ks < 64; ks += 32) {
                uint32_t af[4][4], bf[2][4];
#pragma unroll
                for (int mi = 0; mi < 4; mi++)
                    ldsm_x4(af[mi][0], af[mi][1], af[mi][2], af[mi][3],
                            aBase + mi * 16 * ROWB + ks);
#pragma unroll
                for (int nb = 0; nb < 2; nb++)
                    ldsm_x4(bf[nb][0], bf[nb][1], bf[nb][2], bf[nb][3],
                            bBase + nb * 16 * ROWB + ks);
#pragma unroll
                for (int mi = 0; mi < 4; mi++)
#pragma unroll
                    for (int nj = 0; nj < 4; nj++)
                        mma16816(acc[mi][nj][0], acc[mi][nj][1],
                                 acc[mi][nj][2], acc[mi][nj][3],
                                 af[mi][0], af[mi][1], af[mi][2], af[mi][3],
                                 bf[nj >> 1][(nj & 1) * 2],
                                 bf[nj >> 1][(nj & 1) * 2 + 1]);
            }
        }

        // epilogue: remap rows [t][b] -> output rows [b][t]
        const int g = lane >> 2, tq = lane & 3;
#pragma unroll
        for (int ni = 0; ni < 4; ni++) {
            int col = bn * 128 + wn * 32 + ni * 8 + tq * 2;
            float b0 = __ldg(&bias[col]), b1 = __ldg(&bias[col + 1]);
#pragma unroll
            for (int mi = 0; mi < 4; mi++) {
                int rs = bm * 128 + wm * 64 + mi * 16 + g;
                int orow0 = (rs & 7) * Tt + (rs >> 3);
                int rs2 = rs + 8;
                int orow1 = (rs2 & 7) * Tt + (rs2 >> 3);
                *(float2*)&C[(size_t)orow0 * Vv + col] =
                    make_float2(acc[mi][ni][0] + b0, acc[mi][ni][1] + b1);
                *(float2*)&C[(size_t)orow1 * Vv + col] =
                    make_float2(acc[mi][ni][2] + b0, acc[mi][ni][3] + b1);
            }
        }
    }
}

// ---------------- fused log-softmax (SMEM-resident row) ---------------------
#define LSM_SMEM (Vv * 4)   // 128000 bytes

__global__ __launch_bounds__(256)
void logsoftmax_kernel(float* __restrict__ C) {
    extern __shared__ float rowbuf[];
    __shared__ float red[256];
    const int row = blockIdx.x, tid = threadIdx.x;
    float4* p4 = (float4*)(C + (size_t)row * Vv);
    float4* r4 = (float4*)rowbuf;

    float m = -1e30f;
    for (int i = tid; i < Vv / 4; i += 256) {
        float4 v = p4[i];
        r4[i] = v;
        m = fmaxf(m, fmaxf(fmaxf(v.x, v.y), fmaxf(v.z, v.w)));
    }
    red[tid] = m; __syncthreads();
    for (int s = 128; s > 0; s >>= 1) {
        if (tid < s) red[tid] = fmaxf(red[tid], red[tid + s]);
        __syncthreads();
    }
    m = red[0]; __syncthreads();

    float sum = 0.f;
    for (int i = tid; i < Vv / 4; i += 256) {
        float4 v = r4[i];
        sum += expf(v.x - m) + expf(v.y - m) + expf(v.z - m) + expf(v.w - m);
    }
    red[tid] = sum; __syncthreads();
    for (int s = 128; s > 0; s >>= 1) {
        if (tid < s) red[tid] += red[tid + s];
        __syncthreads();
    }
    float lse = m + logf(red[0]);
    __syncthreads();

    for (int i = tid; i < Vv / 4; i += 256) {
        float4 v = r4[i];
        v.x -= lse; v.y -= lse; v.z -= lse; v.w -= lse;
        p4[i] = v;
    }
}

// ---------------- launcher ---------------------------------------------------
extern "C" void kernel_launch(void* const* d_in, const int* in_sizes, int n_in,
                              void* d_out, int out_size) {
    const int*   idx  = (const int*)d_in[0];
    const float* E    = (const float*)d_in[1];
    const float* W    = (const float*)d_in[2];
    const float* bW   = (const float*)d_in[3];
    const float* U    = (const float*)d_in[4];
    const float* bU   = (const float*)d_in[5];
    const float* Wout = (const float*)d_in[6];
    const float* bout = (const float*)d_in[7];
    float* out = (float*)d_out;

    void* p;
    cudaGetSymbolAddress(&p, g_Xb);    __nv_bfloat16* Xb    = (__nv_bfloat16*)p;
    cudaGetSymbolAddress(&p, g_Wb);    __nv_bfloat16* Wb    = (__nv_bfloat16*)p;
    cudaGetSymbolAddress(&p, g_Ub);    __nv_bfloat16* Ub    = (__nv_bfloat16*)p;
    cudaGetSymbolAddress(&p, g_Woutb); __nv_bfloat16* Woutb = (__nv_bfloat16*)p;
    cudaGetSymbolAddress(&p, g_Wx);    float*         Wx    = (float*)p;
    cudaGetSymbolAddress(&p, g_hsb);   __nv_bfloat16* hsb   = (__nv_bfloat16*)p;

    cudaFuncSetAttribute(gemm_bf16_kernel,
                         cudaFuncAttributeMaxDynamicSharedMemorySize, GEMM_SMEM);
    cudaFuncSetAttribute(fused_rnn_gemm_kernel,
                         cudaFuncAttributeMaxDynamicSharedMemorySize, FUSED_SMEM);
    cudaFuncSetAttribute(logsoftmax_kernel,
                         cudaFuncAttributeMaxDynamicSharedMemorySize, LSM_SMEM);

    // weight conversions + gather + state reset
    f32_to_bf16_kernel<<<512, 256>>>((const float4*)W,
                                     (__nv_bfloat162*)Wb, (Dd * Dd) / 4);
    f32_to_bf16_kernel<<<512, 256>>>((const float4*)U,
                                     (__nv_bfloat162*)Ub, (Dd * Dd) / 4);
    f32_to_bf16_kernel<<<4096, 256>>>((const float4*)Wout,
                                      (__nv_bfloat162*)Woutb, (Vv * Dd) / 4);
    gather_embed_kernel<<<Mrows, 128>>>(idx, E, Xb);
    rnn_reset_kernel<<<64, 256>>>();

    // input projection: Wx = Xb * Wb^T + bW   [2048 x 1024]
    dim3 g1(Mrows / 128, Dd / 128);
    gemm_bf16_kernel<<<g1, 256, GEMM_SMEM>>>(Xb, Wb, bW, Wx, Mrows, Dd, Dd);

    // fused batch-grouped recurrence + overlapped output projection
    fused_rnn_gemm_kernel<<<256, 256, FUSED_SMEM>>>(Wx, bU, hsb,
                                                    Woutb, bout, out);

    // fused log_softmax
    logsoftmax_kernel<<<Mrows, 256, LSM_SMEM>>>(out);
}